// round 17
// baseline (speedup 1.0000x reference)
#include <cuda_runtime.h>
#include <cstdint>
#include <math.h>

// Problem constants
#define Bb 16
#define Tt 2048
#define Cc 512
#define Hh 4
#define Kk 31
#define Mm (Bb * Tt)        // 32768 rows

// ---------------- scratch (device globals: allocation-free) ----------------
__device__ float g_w1c[(size_t)2 * Cc * Cc];  // tf32-rounded w1, 2 MB
__device__ float g_w2c[(size_t)Cc * Cc];      // tf32-rounded w2, 1 MB
__device__ float g_glu[(size_t)Mm * Cc];      // GLU output (fp32), 64 MB
__device__ float g_z[(size_t)Mm * Cc];        // post-conv (tf32-rounded), 64 MB

static __device__ __forceinline__ float f2tf32(float f) {
    uint32_t u;
    asm("cvt.rna.tf32.f32 %0, %1;" : "=r"(u) : "f"(f));
    return __uint_as_float(u);
}

static __device__ __forceinline__ uint32_t smem_u32(const void* p) {
    uint32_t a;
    asm("{ .reg .u64 t; cvta.to.shared.u64 t, %1; cvt.u32.u64 %0, t; }"
        : "=r"(a) : "l"(p));
    return a;
}

#define CP16(d, s) \
    asm volatile("cp.async.cg.shared.global [%0], [%1], 16;" \
                 :: "r"(d), "l"(s) : "memory")

#define MMA_TF32(acc, a0, a1, a2, a3, b0, b1) \
    asm volatile( \
        "mma.sync.aligned.m16n8k8.row.col.f32.tf32.tf32.f32 " \
        "{%0,%1,%2,%3}, {%4,%5,%6,%7}, {%8,%9}, {%0,%1,%2,%3};" \
        : "+f"((acc)[0]), "+f"((acc)[1]), "+f"((acc)[2]), "+f"((acc)[3]) \
        : "r"(__float_as_uint(a0)), "r"(__float_as_uint(a1)), \
          "r"(__float_as_uint(a2)), "r"(__float_as_uint(a3)), \
          "r"(__float_as_uint(b0)), "r"(__float_as_uint(b1)))

// ---------------- prepass: rna-round BOTH weights in one launch ----------------
__global__ void __launch_bounds__(256) cvt_w_kernel(
    const float* __restrict__ w1, float* __restrict__ w1c,
    const float* __restrict__ w2, float* __restrict__ w2c,
    int n1_4, int ntot_4)
{
    int i = blockIdx.x * blockDim.x + threadIdx.x;
    if (i >= ntot_4) return;
    const float4* src;
    float4* dst;
    int idx;
    if (i < n1_4) { src = (const float4*)w1; dst = (float4*)w1c; idx = i; }
    else          { src = (const float4*)w2; dst = (float4*)w2c; idx = i - n1_4; }
    float4 v = src[idx];
    v.x = f2tf32(v.x); v.y = f2tf32(v.y);
    v.z = f2tf32(v.z); v.w = f2tf32(v.w);
    dst[idx] = v;
}

// ---------------- tf32 mma.sync GEMM (R8/R11/R13/R16-verified) ----------------
#define GEMM_SMEM 65536

template<bool GLU, bool CVTA>
__global__ void __launch_bounds__(128, 3) gemm_mma(
    const float* __restrict__ A, const float* __restrict__ Bw,
    const float* __restrict__ bias, float* __restrict__ C)
{
    extern __shared__ __align__(16) float smf[];   // 16384 floats
    const int tid  = threadIdx.x;
    const int lane = tid & 31;
    const int wid  = tid >> 5;
    const int wm   = wid & 1;
    const int wn   = wid >> 1;
    const int bc   = lane & 3;
    const int lq   = lane >> 2;
    const int m0   = blockIdx.y * 128;
    const int colbase = blockIdx.x * (GLU ? 64 : 128);
    const int NK = Cc / 16;

    const int prow  = tid >> 2;
    const int punit = tid & 3;
    const int swu   = (punit ^ (prow & 3)) << 2;
    const uint32_t smu = smem_u32(smf);
    const uint32_t saA = smu + (uint32_t)prow * 64u + (uint32_t)swu * 4u;
    const uint32_t saB = saA + 8192u;
    const char* gA = (const char*)(A + (size_t)(m0 + prow) * Cc + punit * 4);
    const char* gB = (const char*)(Bw + (size_t)(colbase + prow) * Cc + punit * 4);
    const int BO1 = GLU ? 1048576 : 65536;
    const int BO2 = GLU ? 65536   : 131072;
    const int BO3 = GLU ? 1114112 : 196608;

    float acc[4][8][4];
#pragma unroll
    for (int mt = 0; mt < 4; mt++)
#pragma unroll
        for (int nt = 0; nt < 8; nt++)
#pragma unroll
            for (int i = 0; i < 4; i++) acc[mt][nt][i] = 0.f;

    const int lq3 = lq & 3;
    const int uo0 = ((((bc >> 1)    ) ^ lq3) << 2) + (bc & 1) * 2;
    const int uo1 = ((((bc >> 1) + 2) ^ lq3) << 2) + (bc & 1) * 2;
    const int aoff = wm * 1024 + lq * 16;
    const int boff = 2048 + wn * 1024 + lq * 16;

    auto issue = [&](uint32_t so, const char* ga, const char* gb) {
        CP16(saA + so,         ga);
        CP16(saA + so + 2048u, ga + 65536);
        CP16(saA + so + 4096u, ga + 131072);
        CP16(saA + so + 6144u, ga + 196608);
        CP16(saB + so,         gb);
        CP16(saB + so + 2048u, gb + BO1);
        CP16(saB + so + 4096u, gb + BO2);
        CP16(saB + so + 6144u, gb + BO3);
        asm volatile("cp.async.commit_group;" ::: "memory");
    };

    issue(0u,      gA,       gB);
    issue(16384u,  gA + 64,  gB + 64);
    issue(32768u,  gA + 128, gB + 128);

#pragma unroll 1
    for (int kt4 = 0; kt4 < NK; kt4 += 4) {
        const char* ga4 = gA + (size_t)(kt4 + 3) * 64;
        const char* gb4 = gB + (size_t)(kt4 + 3) * 64;
#pragma unroll
        for (int j = 0; j < 4; j++) {
            const int kt = kt4 + j;
            asm volatile("cp.async.wait_group 2;" ::: "memory");
            __syncthreads();
            if (kt + 3 < NK)
                issue((uint32_t)(((j + 3) & 3) * 16384), ga4 + j * 64, gb4 + j * 64);
            else
                asm volatile("cp.async.commit_group;" ::: "memory");

            const float* sA = smf + j * 4096 + aoff;
            const float* sB = smf + j * 4096 + boff;
#pragma unroll
            for (int s = 0; s < 2; s++) {
                const int uo = s ? uo1 : uo0;
                float af[4][4];
#pragma unroll
                for (int mt = 0; mt < 4; mt++) {
                    const float2 v0 = *(const float2*)(sA + uo + mt * 256);
                    const float2 v1 = *(const float2*)(sA + uo + mt * 256 + 128);
                    af[mt][0] = v0.x; af[mt][1] = v1.x;
                    af[mt][2] = v0.y; af[mt][3] = v1.y;
                    if (CVTA) {
                        af[mt][0] = f2tf32(af[mt][0]);
                        af[mt][1] = f2tf32(af[mt][1]);
                        af[mt][2] = f2tf32(af[mt][2]);
                        af[mt][3] = f2tf32(af[mt][3]);
                    }
                }
                float2 bvv[2];
                bvv[0] = *(const float2*)(sB + uo);
#pragma unroll
                for (int nt = 0; nt < 8; nt++) {
                    if (nt < 7)
                        bvv[(nt + 1) & 1] = *(const float2*)(sB + uo + (nt + 1) * 128);
                    const float2 bv = bvv[nt & 1];
#pragma unroll
                    for (int mt = 0; mt < 4; mt++) {
                        MMA_TF32(acc[mt][nt],
                                 af[mt][0], af[mt][1], af[mt][2], af[mt][3],
                                 bv.x, bv.y);
                    }
                }
            }
        }
    }

    // ---- epilogue ----
    if (GLU) {
#pragma unroll
        for (int mt = 0; mt < 4; mt++) {
            const int r = m0 + wm * 64 + mt * 16 + lq;
#pragma unroll
            for (int nt = 0; nt < 4; nt++) {
                const int col = colbase + wn * 32 + nt * 8 + bc * 2;
                const float2 ba = *(const float2*)&bias[col];
                const float2 bg = *(const float2*)&bias[512 + col];
                float2 o;
                {
                    const float a0 = acc[mt][nt][0] + ba.x, a1 = acc[mt][nt][1] + ba.y;
                    const float g0 = acc[mt][nt + 4][0] + bg.x, g1 = acc[mt][nt + 4][1] + bg.y;
                    o.x = a0 / (1.f + __expf(-g0));
                    o.y = a1 / (1.f + __expf(-g1));
                    *(float2*)&C[(size_t)r * Cc + col] = o;
                }
                {
                    const float a0 = acc[mt][nt][2] + ba.x, a1 = acc[mt][nt][3] + ba.y;
                    const float g0 = acc[mt][nt + 4][2] + bg.x, g1 = acc[mt][nt + 4][3] + bg.y;
                    o.x = a0 / (1.f + __expf(-g0));
                    o.y = a1 / (1.f + __expf(-g1));
                    *(float2*)&C[(size_t)(r + 8) * Cc + col] = o;
                }
            }
        }
    } else {
#pragma unroll
        for (int mt = 0; mt < 4; mt++) {
            const int r = m0 + wm * 64 + mt * 16 + lq;
#pragma unroll
            for (int nt = 0; nt < 8; nt++) {
                const int col = colbase + wn * 64 + nt * 8 + bc * 2;
                const float2 bb = *(const float2*)&bias[col];
                float2 o;
                o.x = acc[mt][nt][0] + bb.x;
                o.y = acc[mt][nt][1] + bb.y;
                *(float2*)&C[(size_t)r * Cc + col] = o;
                o.x = acc[mt][nt][2] + bb.x;
                o.y = acc[mt][nt][3] + bb.y;
                *(float2*)&C[(size_t)(r + 8) * Cc + col] = o;
            }
        }
    }
}

// ---------------- depthwise LightConv via tensor cores (Toeplitz MMA) ----------
// out[t,c] = bias[c] + sum_q A_h[m][q] * s[I0+q][c],  A_h[m][q] = w_h[q-m]
// (0<=q-m<=30 else 0), h = c%4.  Tile 64t x 64c, warp = class h (16 channels,
// strided 4).  Per warp: 4 t-groups x 2 n-groups x 6 k-steps = 48 MMAs.
// D de-permuted through smem, stored coalesced with +bias and f2tf32
// (same rounding point as the scalar version).  s rows padded to 96 so the
// zero-weight q=46,47 columns read in-bounds.
#define CT 64                 // t-tile
#define CPAD 15
#define CSR 96                // padded rows (64 + 30 halo + 2 k-pad)

__global__ __launch_bounds__(128, 4) void lconv_mma_kernel(
    const float* __restrict__ glu, const float* __restrict__ lw,
    const float* __restrict__ lbias, float* __restrict__ z)
{
    __shared__ float s[CSR][65];     // odd stride: conflict-light scalar access
    __shared__ float outs[CT][64];   // de-permute staging
    __shared__ float wk[Hh][Kk];

    const int tid = threadIdx.x;
    const int t0 = blockIdx.x * CT;
    const int c0 = blockIdx.y * 64;
    const int b  = blockIdx.z;

    // softmax of the 4 shared kernels
    if (tid < Hh) {
        float mx = -1e30f;
#pragma unroll
        for (int k = 0; k < Kk; k++) mx = fmaxf(mx, lw[tid * Kk + k]);
        float sum = 0.f;
        float e[Kk];
#pragma unroll
        for (int k = 0; k < Kk; k++) { e[k] = __expf(lw[tid * Kk + k] - mx); sum += e[k]; }
        const float inv = 1.f / sum;
#pragma unroll
        for (int k = 0; k < Kk; k++) wk[tid][k] = e[k] * inv;
    }

    // load tile rows [t0-15, t0+80]; zero outside [0, Tt)
    const float* yb = glu + (size_t)b * Tt * Cc;
    for (int idx = tid; idx < CSR * 16; idx += 128) {
        const int r = idx >> 4;
        const int v = idx & 15;
        const int t = t0 - CPAD + r;
        float4 o;
        if (t >= 0 && t < Tt) o = *(const float4*)&yb[(size_t)t * Cc + c0 + v * 4];
        else { o.x = o.y = o.z = o.w = 0.f; }
        s[r][v * 4 + 0] = o.x;
        s[r][v * 4 + 1] = o.y;
        s[r][v * 4 + 2] = o.z;
        s[r][v * 4 + 3] = o.w;
    }
    __syncthreads();

    const int h    = tid >> 5;       // warp = kernel class
    const int lane = tid & 31;
    const int r1   = lane >> 2;      // A row low / B n-index
    const int kq0  = (lane & 3) * 2; // k-pair base / D col base

    // A fragments (Toeplitz, shift-invariant => shared by all t-groups)
    float afr[6][4];
#pragma unroll
    for (int kk = 0; kk < 6; kk++) {
        const int q0 = kk * 8 + kq0;
        const int d0 = q0 - r1;
        const int d1 = q0 - r1 - 8;
        const int d2 = q0 + 1 - r1;
        const int d3 = q0 + 1 - r1 - 8;
        afr[kk][0] = (d0 >= 0 && d0 <= 30) ? f2tf32(wk[h][d0]) : 0.f;
        afr[kk][1] = (d1 >= 0 && d1 <= 30) ? f2tf32(wk[h][d1]) : 0.f;
        afr[kk][2] = (d2 >= 0 && d2 <= 30) ? f2tf32(wk[h][d2]) : 0.f;
        afr[kk][3] = (d3 >= 0 && d3 <= 30) ? f2tf32(wk[h][d3]) : 0.f;
    }

    // 8 accumulator tiles: [tg 0..3][ng 0..1]
    float acc[4][2][4];
#pragma unroll
    for (int tg = 0; tg < 4; tg++)
#pragma unroll
        for (int ng = 0; ng < 2; ng++)
#pragma unroll
            for (int i = 0; i < 4; i++) acc[tg][ng][i] = 0.f;

    const int cB0 = h + 4 * r1;      // B smem col for ng=0; ng=1 adds 32
#pragma unroll
    for (int kk = 0; kk < 6; kk++) {
        const int rw = kk * 8 + kq0;
        float bfr[4][2][2];
#pragma unroll
        for (int tg = 0; tg < 4; tg++) {
            const int row = tg * 16 + rw;
#pragma unroll
            for (int ng = 0; ng < 2; ng++) {
                bfr[tg][ng][0] = s[row][cB0 + 32 * ng];
                bfr[tg][ng][1] = s[row + 1][cB0 + 32 * ng];
            }
        }
#pragma unroll
        for (int tg = 0; tg < 4; tg++)
#pragma unroll
            for (int ng = 0; ng < 2; ng++)
                MMA_TF32(acc[tg][ng],
                         afr[kk][0], afr[kk][1], afr[kk][2], afr[kk][3],
                         bfr[tg][ng][0], bfr[tg][ng][1]);
    }

    // de-permute: D(row lq/+8, col 2(lane&3)+d) -> channel h + 4*(ng*8+kq0+d)
#pragma unroll
    for (int tg = 0; tg < 4; tg++)
#pragma unroll
        for (int ng = 0; ng < 2; ng++) {
            const int cc = h + 4 * (ng * 8 + kq0);
            outs[tg * 16 + r1][cc]         = acc[tg][ng][0];
            outs[tg * 16 + r1][cc + 4]     = acc[tg][ng][1];
            outs[tg * 16 + r1 + 8][cc]     = acc[tg][ng][2];
            outs[tg * 16 + r1 + 8][cc + 4] = acc[tg][ng][3];
        }
    __syncthreads();

    // coalesced store: + bias, tf32-round (same rounding point as scalar conv)
    float* zb = z + ((size_t)b * Tt + t0) * Cc + c0;
    for (int idx = tid; idx < CT * 16; idx += 128) {
        const int row = idx >> 4;
        const int v = idx & 15;
        const float4 a = *(const float4*)&outs[row][v * 4];
        const float4 bi = *(const float4*)&lbias[c0 + v * 4];
        float4 o;
        o.x = f2tf32(a.x + bi.x);
        o.y = f2tf32(a.y + bi.y);
        o.z = f2tf32(a.z + bi.z);
        o.w = f2tf32(a.w + bi.w);
        *(float4*)&zb[(size_t)row * Cc + v * 4] = o;
    }
}

// ---------------- launch ----------------
extern "C" void kernel_launch(void* const* d_in, const int* in_sizes, int n_in,
                              void* d_out, int out_size)
{
    const float* x     = (const float*)d_in[0];
    const float* lw    = (const float*)d_in[1];
    const float* lbias = (const float*)d_in[2];
    const float* w1    = (const float*)d_in[3];
    const float* b1    = (const float*)d_in[4];
    const float* w2    = (const float*)d_in[5];
    const float* b2    = (const float*)d_in[6];
    float* out = (float*)d_out;

    float *w1c, *w2c, *glup, *zp;
    cudaGetSymbolAddress((void**)&w1c,  g_w1c);
    cudaGetSymbolAddress((void**)&w2c,  g_w2c);
    cudaGetSymbolAddress((void**)&glup, g_glu);
    cudaGetSymbolAddress((void**)&zp,   g_z);

    cudaFuncSetAttribute((const void*)gemm_mma<true, false>,
                         cudaFuncAttributeMaxDynamicSharedMemorySize, GEMM_SMEM);
    cudaFuncSetAttribute((const void*)gemm_mma<false, false>,
                         cudaFuncAttributeMaxDynamicSharedMemorySize, GEMM_SMEM);

    // prepass: rna-round both weights in ONE launch
    const int n1_4 = 2 * Cc * Cc / 4;
    const int ntot_4 = n1_4 + Cc * Cc / 4;
    cvt_w_kernel<<<(ntot_4 + 255) / 256, 256>>>(w1, w1c, w2, w2c, n1_4, ntot_4);

    // GEMM1 + bias + GLU (A = raw x; HMMA.tf32 truncation semantics)
    gemm_mma<true, false><<<dim3(Cc / 64, Mm / 128), 128, GEMM_SMEM>>>(x, w1c, b1, glup);

    // depthwise LightConv + bias via tensor cores (+ tf32 rounding of z)
    lconv_mma_kernel<<<dim3(Tt / CT, Cc / 64, Bb), 128>>>(glup, lw, lbias, zp);

    // GEMM2 + bias (128x128 champion config; A = z, pre-rounded by conv)
    gemm_mma<false, false><<<dim3(Cc / 128, Mm / 128), 128, GEMM_SMEM>>>(zp, w2c, b2, out);
}